// round 12
// baseline (speedup 1.0000x reference)
#include <cuda_runtime.h>
#include <cstdint>

// Local_Mask: x [32,512,56,56] f32, T [32,512,1,1] i32 (0/1).
// Per channel: argmax location (mi,mj) over HxW (first occurrence),
// box rows [max(mi-3,0), min(mi+3,55)) x cols [max(mj-3,0), min(mj+3,55)),
// if T>0: out = 0 inside box, x * lam outside, lam = 3136/(3136-area).
// else out = x.
//
// One CTA per channel. 3136 floats = 784 float4. 256 threads, <=4 float4
// per thread held in registers (load once, write once => single-pass,
// 411 MB total HBM traffic).

static constexpr int HW4   = 784;   // 3136 / 4
static constexpr int H     = 56;
static constexpr int W4    = 14;    // 56 / 4
static constexpr int HWTOT = 3136;

__global__ __launch_bounds__(256, 8)
void local_mask_kernel(const float4* __restrict__ x,
                       const int*    __restrict__ T,
                       float4*       __restrict__ out)
{
    const int c   = blockIdx.x;
    const int tid = threadIdx.x;
    const float4* xc = x   + (size_t)c * HW4;
    float4*       oc = out + (size_t)c * HW4;

    const int tval = T[c];  // broadcast L1 hit

    // ---- load (registers only) + local argmax, first-occurrence ----
    float4 v[4];
    float bestv = -__int_as_float(0x7f800000);  // -inf
    int   besti = 0x7fffffff;

    #pragma unroll
    for (int k = 0; k < 4; k++) {
        const int j = tid + k * 256;
        if (j < HW4) {
            float4 t = xc[j];
            v[k] = t;
            const int base = j * 4;
            // increasing-index scan with strict '>' keeps first occurrence
            if (t.x > bestv) { bestv = t.x; besti = base;     }
            if (t.y > bestv) { bestv = t.y; besti = base + 1; }
            if (t.z > bestv) { bestv = t.z; besti = base + 2; }
            if (t.w > bestv) { bestv = t.w; besti = base + 3; }
        }
    }

    // ---- warp reduce (val desc, idx asc tie-break) ----
    #pragma unroll
    for (int off = 16; off > 0; off >>= 1) {
        float ov = __shfl_down_sync(0xffffffffu, bestv, off);
        int   oi = __shfl_down_sync(0xffffffffu, besti, off);
        if (ov > bestv || (ov == bestv && oi < besti)) { bestv = ov; besti = oi; }
    }

    // ---- cross-warp reduce via tiny smem ----
    __shared__ float sv[8];
    __shared__ int   si[8];
    __shared__ int   sidx;

    const int lane = tid & 31;
    const int wid  = tid >> 5;
    if (lane == 0) { sv[wid] = bestv; si[wid] = besti; }
    __syncthreads();

    if (tid == 0) {
        float bv = sv[0]; int bi = si[0];
        #pragma unroll
        for (int w = 1; w < 8; w++) {
            if (sv[w] > bv || (sv[w] == bv && si[w] < bi)) { bv = sv[w]; bi = si[w]; }
        }
        sidx = bi;
    }
    __syncthreads();

    const int idx = sidx;

    // ---- box + lambda ----
    const int mi = idx / H;      // reference uses H for both div and mod
    const int mj = idx % H;
    const int h1 = max(mi - 3, 0);
    const int h2 = min(mi + 3, H - 1);
    const int w1 = max(mj - 3, 0);
    const int w2 = min(mj + 3, H - 1);
    const int area = (h2 - h1) * (w2 - w1);
    const float lam = (float)HWTOT / (float)(HWTOT - area);
    const bool marked = (tval > 0);

    // ---- masked write from registers ----
    #pragma unroll
    for (int k = 0; k < 4; k++) {
        const int j = tid + k * 256;
        if (j < HW4) {
            float4 o = v[k];
            if (marked) {
                const int row = j / W4;            // compiler -> magic-number mult
                const int cb  = (j - row * W4) * 4;
                const bool inrow = (row >= h1) & (row < h2);
                o.x = (inrow & (cb     >= w1) & (cb     < w2)) ? 0.0f : o.x * lam;
                o.y = (inrow & (cb + 1 >= w1) & (cb + 1 < w2)) ? 0.0f : o.y * lam;
                o.z = (inrow & (cb + 2 >= w1) & (cb + 2 < w2)) ? 0.0f : o.z * lam;
                o.w = (inrow & (cb + 3 >= w1) & (cb + 3 < w2)) ? 0.0f : o.w * lam;
            }
            oc[j] = o;
        }
    }
}

extern "C" void kernel_launch(void* const* d_in, const int* in_sizes, int n_in,
                              void* d_out, int out_size)
{
    const float4* x = (const float4*)d_in[0];   // 32*512*56*56 f32
    const int*    T = (const int*)d_in[1];      // 32*512 i32
    float4*       o = (float4*)d_out;

    const int channels = in_sizes[1];           // 16384
    local_mask_kernel<<<channels, 256>>>(x, T, o);
}

// round 13
// speedup vs baseline: 1.0040x; 1.0040x over previous
#include <cuda_runtime.h>
#include <cstdint>

// Local_Mask: x [32,512,56,56] f32, T [32,512,1,1] i32 (0/1).
// Per channel: argmax location (mi,mj) over HxW (first occurrence),
// box rows [max(mi-3,0), min(mi+3,55)) x cols [max(mj-3,0), min(mj+3,55)),
// if T>0: out = 0 inside box, x * lam outside, lam = 3136/(3136-area).
// else out = x.
//
// One CTA per channel. 3136 floats = 784 float4. 256 threads, <=4 float4
// per thread held in registers (load once, write once => single-pass,
// 411 MB total HBM traffic).

static constexpr int HW4   = 784;   // 3136 / 4
static constexpr int H     = 56;
static constexpr int W4    = 14;    // 56 / 4
static constexpr int HWTOT = 3136;

__global__ __launch_bounds__(256, 8)
void local_mask_kernel(const float4* __restrict__ x,
                       const int*    __restrict__ T,
                       float4*       __restrict__ out)
{
    const int c   = blockIdx.x;
    const int tid = threadIdx.x;
    const float4* xc = x   + (size_t)c * HW4;
    float4*       oc = out + (size_t)c * HW4;

    const int tval = T[c];  // broadcast L1 hit

    // ---- load (registers only) + local argmax, first-occurrence ----
    float4 v[4];
    float bestv = -__int_as_float(0x7f800000);  // -inf
    int   besti = 0x7fffffff;

    #pragma unroll
    for (int k = 0; k < 4; k++) {
        const int j = tid + k * 256;
        if (j < HW4) {
            float4 t = xc[j];
            v[k] = t;
            const int base = j * 4;
            // increasing-index scan with strict '>' keeps first occurrence
            if (t.x > bestv) { bestv = t.x; besti = base;     }
            if (t.y > bestv) { bestv = t.y; besti = base + 1; }
            if (t.z > bestv) { bestv = t.z; besti = base + 2; }
            if (t.w > bestv) { bestv = t.w; besti = base + 3; }
        }
    }

    // ---- warp reduce (val desc, idx asc tie-break) ----
    #pragma unroll
    for (int off = 16; off > 0; off >>= 1) {
        float ov = __shfl_down_sync(0xffffffffu, bestv, off);
        int   oi = __shfl_down_sync(0xffffffffu, besti, off);
        if (ov > bestv || (ov == bestv && oi < besti)) { bestv = ov; besti = oi; }
    }

    // ---- cross-warp reduce via tiny smem ----
    __shared__ float sv[8];
    __shared__ int   si[8];
    __shared__ int   sidx;

    const int lane = tid & 31;
    const int wid  = tid >> 5;
    if (lane == 0) { sv[wid] = bestv; si[wid] = besti; }
    __syncthreads();

    if (tid == 0) {
        float bv = sv[0]; int bi = si[0];
        #pragma unroll
        for (int w = 1; w < 8; w++) {
            if (sv[w] > bv || (sv[w] == bv && si[w] < bi)) { bv = sv[w]; bi = si[w]; }
        }
        sidx = bi;
    }
    __syncthreads();

    const int idx = sidx;

    // ---- box + lambda ----
    const int mi = idx / H;      // reference uses H for both div and mod
    const int mj = idx % H;
    const int h1 = max(mi - 3, 0);
    const int h2 = min(mi + 3, H - 1);
    const int w1 = max(mj - 3, 0);
    const int w2 = min(mj + 3, H - 1);
    const int area = (h2 - h1) * (w2 - w1);
    const float lam = (float)HWTOT / (float)(HWTOT - area);
    const bool marked = (tval > 0);

    // ---- masked write from registers ----
    #pragma unroll
    for (int k = 0; k < 4; k++) {
        const int j = tid + k * 256;
        if (j < HW4) {
            float4 o = v[k];
            if (marked) {
                const int row = j / W4;            // compiler -> magic-number mult
                const int cb  = (j - row * W4) * 4;
                const bool inrow = (row >= h1) & (row < h2);
                o.x = (inrow & (cb     >= w1) & (cb     < w2)) ? 0.0f : o.x * lam;
                o.y = (inrow & (cb + 1 >= w1) & (cb + 1 < w2)) ? 0.0f : o.y * lam;
                o.z = (inrow & (cb + 2 >= w1) & (cb + 2 < w2)) ? 0.0f : o.z * lam;
                o.w = (inrow & (cb + 3 >= w1) & (cb + 3 < w2)) ? 0.0f : o.w * lam;
            }
            oc[j] = o;
        }
    }
}

extern "C" void kernel_launch(void* const* d_in, const int* in_sizes, int n_in,
                              void* d_out, int out_size)
{
    const float4* x = (const float4*)d_in[0];   // 32*512*56*56 f32
    const int*    T = (const int*)d_in[1];      // 32*512 i32
    float4*       o = (float4*)d_out;

    const int channels = in_sizes[1];           // 16384
    local_mask_kernel<<<channels, 256>>>(x, T, o);
}

// round 14
// speedup vs baseline: 1.0050x; 1.0010x over previous
#include <cuda_runtime.h>
#include <cstdint>

// Local_Mask: x [32,512,56,56] f32, T [32,512,1,1] i32 (0/1).
// Per channel: argmax location (mi,mj) over HxW (first occurrence),
// box rows [max(mi-3,0), min(mi+3,55)) x cols [max(mj-3,0), min(mj+3,55)),
// if T>0: out = 0 inside box, x * lam outside, lam = 3136/(3136-area).
// else out = x.
//
// One CTA per channel. 3136 floats = 784 float4. 256 threads, <=4 float4
// per thread held in registers (load once, write once => single-pass,
// 411 MB total HBM traffic).

static constexpr int HW4   = 784;   // 3136 / 4
static constexpr int H     = 56;
static constexpr int W4    = 14;    // 56 / 4
static constexpr int HWTOT = 3136;

__global__ __launch_bounds__(256, 8)
void local_mask_kernel(const float4* __restrict__ x,
                       const int*    __restrict__ T,
                       float4*       __restrict__ out)
{
    const int c   = blockIdx.x;
    const int tid = threadIdx.x;
    const float4* xc = x   + (size_t)c * HW4;
    float4*       oc = out + (size_t)c * HW4;

    const int tval = T[c];  // broadcast L1 hit

    // ---- load (registers only) + local argmax, first-occurrence ----
    float4 v[4];
    float bestv = -__int_as_float(0x7f800000);  // -inf
    int   besti = 0x7fffffff;

    #pragma unroll
    for (int k = 0; k < 4; k++) {
        const int j = tid + k * 256;
        if (j < HW4) {
            float4 t = xc[j];
            v[k] = t;
            const int base = j * 4;
            // increasing-index scan with strict '>' keeps first occurrence
            if (t.x > bestv) { bestv = t.x; besti = base;     }
            if (t.y > bestv) { bestv = t.y; besti = base + 1; }
            if (t.z > bestv) { bestv = t.z; besti = base + 2; }
            if (t.w > bestv) { bestv = t.w; besti = base + 3; }
        }
    }

    // ---- warp reduce (val desc, idx asc tie-break) ----
    #pragma unroll
    for (int off = 16; off > 0; off >>= 1) {
        float ov = __shfl_down_sync(0xffffffffu, bestv, off);
        int   oi = __shfl_down_sync(0xffffffffu, besti, off);
        if (ov > bestv || (ov == bestv && oi < besti)) { bestv = ov; besti = oi; }
    }

    // ---- cross-warp reduce via tiny smem ----
    __shared__ float sv[8];
    __shared__ int   si[8];
    __shared__ int   sidx;

    const int lane = tid & 31;
    const int wid  = tid >> 5;
    if (lane == 0) { sv[wid] = bestv; si[wid] = besti; }
    __syncthreads();

    if (tid == 0) {
        float bv = sv[0]; int bi = si[0];
        #pragma unroll
        for (int w = 1; w < 8; w++) {
            if (sv[w] > bv || (sv[w] == bv && si[w] < bi)) { bv = sv[w]; bi = si[w]; }
        }
        sidx = bi;
    }
    __syncthreads();

    const int idx = sidx;

    // ---- box + lambda ----
    const int mi = idx / H;      // reference uses H for both div and mod
    const int mj = idx % H;
    const int h1 = max(mi - 3, 0);
    const int h2 = min(mi + 3, H - 1);
    const int w1 = max(mj - 3, 0);
    const int w2 = min(mj + 3, H - 1);
    const int area = (h2 - h1) * (w2 - w1);
    const float lam = (float)HWTOT / (float)(HWTOT - area);
    const bool marked = (tval > 0);

    // ---- masked write from registers ----
    #pragma unroll
    for (int k = 0; k < 4; k++) {
        const int j = tid + k * 256;
        if (j < HW4) {
            float4 o = v[k];
            if (marked) {
                const int row = j / W4;            // compiler -> magic-number mult
                const int cb  = (j - row * W4) * 4;
                const bool inrow = (row >= h1) & (row < h2);
                o.x = (inrow & (cb     >= w1) & (cb     < w2)) ? 0.0f : o.x * lam;
                o.y = (inrow & (cb + 1 >= w1) & (cb + 1 < w2)) ? 0.0f : o.y * lam;
                o.z = (inrow & (cb + 2 >= w1) & (cb + 2 < w2)) ? 0.0f : o.z * lam;
                o.w = (inrow & (cb + 3 >= w1) & (cb + 3 < w2)) ? 0.0f : o.w * lam;
            }
            oc[j] = o;
        }
    }
}

extern "C" void kernel_launch(void* const* d_in, const int* in_sizes, int n_in,
                              void* d_out, int out_size)
{
    const float4* x = (const float4*)d_in[0];   // 32*512*56*56 f32
    const int*    T = (const int*)d_in[1];      // 32*512 i32
    float4*       o = (float4*)d_out;

    const int channels = in_sizes[1];           // 16384
    local_mask_kernel<<<channels, 256>>>(x, T, o);
}